// round 8
// baseline (speedup 1.0000x reference)
#include <cuda_runtime.h>
#include <cuda_bf16.h>
#include <stdint.h>

#define N_NODES 100000
#define N_EDGES 1200000
#define D 64

// Persistent scratch: h = x + scatter_sum(relu(x[src] + e))
// 16B-aligned: red.global.add.v4.f32 requires 16B-aligned addresses.
__device__ __align__(16) float g_h[(size_t)N_NODES * D];

// ---------------------------------------------------------------------------
// Kernel 1: seed h with x  (EPS = 0  ->  h = 1.0*x + agg)
// ---------------------------------------------------------------------------
__global__ void init_h_kernel(const float* __restrict__ x) {
    int i = blockIdx.x * blockDim.x + threadIdx.x;   // float4 index
    const int n4 = N_NODES * D / 4;                  // 1.6M
    if (i < n4) {
        reinterpret_cast<float4*>(g_h)[i] =
            reinterpret_cast<const float4*>(x)[i];
    }
}

// ---------------------------------------------------------------------------
// Kernel 2: per-edge message + scatter reduce.
// 16 threads per edge, each owning one float4 chunk of the 64-wide feature.
//   msg = relu(x[src] + edge_attr[e]);  red.global.add.v4 into g_h[dst].
// edge_index is int32.
// ---------------------------------------------------------------------------
__global__ void edge_kernel(const float* __restrict__ x,
                            const int* __restrict__ ei,
                            const float* __restrict__ ea) {
    int t = blockIdx.x * blockDim.x + threadIdx.x;
    const int total = N_EDGES * 16;
    if (t >= total) return;
    int e = t >> 4;        // edge id
    int c = t & 15;        // float4 chunk within row

    int src = ei[e];
    int dst = ei[N_EDGES + e];

    float4 xv = reinterpret_cast<const float4*>(x + (size_t)src * D)[c];
    float4 ev = reinterpret_cast<const float4*>(ea + (size_t)e * D)[c];

    float4 m;
    m.x = fmaxf(xv.x + ev.x, 0.0f);
    m.y = fmaxf(xv.y + ev.y, 0.0f);
    m.z = fmaxf(xv.z + ev.z, 0.0f);
    m.w = fmaxf(xv.w + ev.w, 0.0f);

    float* p = g_h + (size_t)dst * D + c * 4;
    asm volatile("red.global.add.v4.f32 [%0], {%1, %2, %3, %4};"
                 :: "l"(p), "f"(m.x), "f"(m.y), "f"(m.z), "f"(m.w)
                 : "memory");
}

// ---------------------------------------------------------------------------
// Kernel 3: tiled per-block MLP.  out = relu(h @ W1 + b1) @ W2 + b2
//
// Block = 128 threads handles TILE_N = 32 nodes (100000 = 3125 * 32 exactly).
// h tile staged in smem with padded stride (bank-conflict-free scalar
// broadcasts). Each thread computes 4 nodes x 4 cols = 4 float4 accumulators
// (registers only -> no local-memory spill). Layer-1 result is written back
// into the h tile between syncs so total smem stays under the 48 KB static cap.
// ---------------------------------------------------------------------------
#define TILE_N 32
#define HPAD 68          // padded row stride (floats); 68 % 4 == 0 (float4 ok)

__global__ void __launch_bounds__(128)
mlp_kernel(const float* __restrict__ W1, const float* __restrict__ b1,
           const float* __restrict__ W2, const float* __restrict__ b2,
           float* __restrict__ out) {
    __shared__ float hs[TILE_N * HPAD];          // 8.5 KB
    __shared__ float W1s[D * D];                 // 16 KB
    __shared__ float W2s[D * D];                 // 16 KB
    __shared__ float b1s[D];
    __shared__ float b2s[D];

    const int tid = threadIdx.x;
    const int node0 = blockIdx.x * TILE_N;

    // Stage weights (float4 copies) and biases.
    {
        const float4* w1g = reinterpret_cast<const float4*>(W1);
        const float4* w2g = reinterpret_cast<const float4*>(W2);
        float4* w1s = reinterpret_cast<float4*>(W1s);
        float4* w2s = reinterpret_cast<float4*>(W2s);
        #pragma unroll
        for (int i = tid; i < D * D / 4; i += 128) {
            w1s[i] = w1g[i];
            w2s[i] = w2g[i];
        }
        if (tid < D) { b1s[tid] = b1[tid]; b2s[tid] = b2[tid]; }
    }

    // Stage h tile: 32 nodes x 16 float4 = 512 float4, 4 per thread.
    {
        const float4* hg = reinterpret_cast<const float4*>(g_h);
        #pragma unroll
        for (int i = tid; i < TILE_N * (D / 4); i += 128) {
            int n = i >> 4;          // node within tile
            int c = i & 15;          // float4 chunk
            float4 v = hg[(size_t)(node0 + n) * (D / 4) + c];
            *reinterpret_cast<float4*>(&hs[n * HPAD + c * 4]) = v;
        }
    }
    __syncthreads();

    const int cg = tid & 15;         // column group: cols cg*4 .. cg*4+3
    const int ng = tid >> 4;         // node group:   nodes ng*4 .. ng*4+3
    const float4* W1s4 = reinterpret_cast<const float4*>(W1s);
    const float4* W2s4 = reinterpret_cast<const float4*>(W2s);

    float4 acc[4];

    // ---- Layer 1: t = relu(h @ W1 + b1) ----
    {
        float4 bv = reinterpret_cast<const float4*>(b1s)[cg];
        #pragma unroll
        for (int n = 0; n < 4; ++n) acc[n] = bv;

        #pragma unroll
        for (int k = 0; k < D; ++k) {
            float4 w = W1s4[k * (D / 4) + cg];
            #pragma unroll
            for (int n = 0; n < 4; ++n) {
                float hk = hs[(ng * 4 + n) * HPAD + k];
                acc[n].x = fmaf(hk, w.x, acc[n].x);
                acc[n].y = fmaf(hk, w.y, acc[n].y);
                acc[n].z = fmaf(hk, w.z, acc[n].z);
                acc[n].w = fmaf(hk, w.w, acc[n].w);
            }
        }
        #pragma unroll
        for (int n = 0; n < 4; ++n) {
            acc[n].x = fmaxf(acc[n].x, 0.0f);
            acc[n].y = fmaxf(acc[n].y, 0.0f);
            acc[n].z = fmaxf(acc[n].z, 0.0f);
            acc[n].w = fmaxf(acc[n].w, 0.0f);
        }
    }
    __syncthreads();   // everyone done reading hs

    // Write t back into hs (same padded layout).
    #pragma unroll
    for (int n = 0; n < 4; ++n)
        *reinterpret_cast<float4*>(&hs[(ng * 4 + n) * HPAD + cg * 4]) = acc[n];
    __syncthreads();

    // ---- Layer 2: out = t @ W2 + b2 ----
    {
        float4 bv = reinterpret_cast<const float4*>(b2s)[cg];
        #pragma unroll
        for (int n = 0; n < 4; ++n) acc[n] = bv;

        #pragma unroll
        for (int k = 0; k < D; ++k) {
            float4 w = W2s4[k * (D / 4) + cg];
            #pragma unroll
            for (int n = 0; n < 4; ++n) {
                float hk = hs[(ng * 4 + n) * HPAD + k];
                acc[n].x = fmaf(hk, w.x, acc[n].x);
                acc[n].y = fmaf(hk, w.y, acc[n].y);
                acc[n].z = fmaf(hk, w.z, acc[n].z);
                acc[n].w = fmaf(hk, w.w, acc[n].w);
            }
        }
    }

    // Store results (coalesced float4 per node row).
    #pragma unroll
    for (int n = 0; n < 4; ++n) {
        int node = node0 + ng * 4 + n;
        reinterpret_cast<float4*>(out + (size_t)node * D)[cg] = acc[n];
    }
}

// ---------------------------------------------------------------------------
// Launch. Inputs: x f32[100000*64], edge_index i32[2*1200000],
// edge_attr f32[1200000*64], W1 f32[64*64], b1 f32[64], W2 f32[64*64],
// b2 f32[64]. Output f32[100000*64].
// ---------------------------------------------------------------------------
extern "C" void kernel_launch(void* const* d_in, const int* in_sizes, int n_in,
                              void* d_out, int out_size) {
    const float* x   = (const float*)d_in[0];
    const int*   ei  = (const int*)d_in[1];
    const float* ea  = (const float*)d_in[2];
    const float* W1  = (const float*)d_in[3];
    const float* b1  = (const float*)d_in[4];
    const float* W2  = (const float*)d_in[5];
    const float* b2  = (const float*)d_in[6];
    float*       out = (float*)d_out;

    {   // h <- x
        int n4 = N_NODES * D / 4;
        init_h_kernel<<<(n4 + 255) / 256, 256>>>(x);
    }
    {   // scatter-sum messages
        int total = N_EDGES * 16;
        edge_kernel<<<(total + 255) / 256, 256>>>(x, ei, ea);
    }
    {   // MLP: 100000 / 32 = 3125 blocks
        mlp_kernel<<<N_NODES / TILE_N, 128>>>(W1, b1, W2, b2, out);
    }
}

// round 9
// speedup vs baseline: 1.0132x; 1.0132x over previous
#include <cuda_runtime.h>
#include <cuda_bf16.h>
#include <stdint.h>

#define N_NODES 100000
#define N_EDGES 1200000
#define D 64

// Persistent scratch: agg = scatter_sum(relu(x[src] + e)); zeroed by memset
// each call. 16B-aligned for red.global.add.v4.f32.
__device__ __align__(16) float g_agg[(size_t)N_NODES * D];

// ---------------------------------------------------------------------------
// f32x2 packed-FMA helpers (FFMA2 — PTX-only, sm_100+)
// ---------------------------------------------------------------------------
__device__ __forceinline__ unsigned long long pk2(float lo, float hi) {
    unsigned long long r;
    asm("mov.b64 %0, {%1, %2};" : "=l"(r) : "f"(lo), "f"(hi));
    return r;
}
__device__ __forceinline__ unsigned long long ffma2(unsigned long long a,
                                                    unsigned long long b,
                                                    unsigned long long c) {
    unsigned long long d;
    asm("fma.rn.f32x2 %0, %1, %2, %3;" : "=l"(d) : "l"(a), "l"(b), "l"(c));
    return d;
}
__device__ __forceinline__ void upk2(unsigned long long v, float& lo, float& hi) {
    asm("mov.b64 {%0, %1}, %2;" : "=f"(lo), "=f"(hi) : "l"(v));
}

// ---------------------------------------------------------------------------
// Kernel 1: per-edge message + scatter reduce.
// 16 threads per edge, one float4 chunk each.
//   msg = relu(x[src] + edge_attr[e]);  red.global.add.v4 into g_agg[dst].
// edge_attr is a one-shot stream -> __ldcs (evict-first) so x and g_agg keep
// their L2 residency. Kernel is L2-transit bound (~768B/edge through LTS).
// ---------------------------------------------------------------------------
__global__ void edge_kernel(const float* __restrict__ x,
                            const int* __restrict__ ei,
                            const float* __restrict__ ea) {
    int t = blockIdx.x * blockDim.x + threadIdx.x;
    const int total = N_EDGES * 16;
    if (t >= total) return;
    int e = t >> 4;        // edge id
    int c = t & 15;        // float4 chunk within row

    int src = __ldg(ei + e);
    int dst = __ldg(ei + N_EDGES + e);

    float4 xv = __ldg(reinterpret_cast<const float4*>(x) + (size_t)src * (D / 4) + c);
    float4 ev = __ldcs(reinterpret_cast<const float4*>(ea) + (size_t)e * (D / 4) + c);

    float4 m;
    m.x = fmaxf(xv.x + ev.x, 0.0f);
    m.y = fmaxf(xv.y + ev.y, 0.0f);
    m.z = fmaxf(xv.z + ev.z, 0.0f);
    m.w = fmaxf(xv.w + ev.w, 0.0f);

    float* p = g_agg + (size_t)dst * D + c * 4;
    asm volatile("red.global.add.v4.f32 [%0], {%1, %2, %3, %4};"
                 :: "l"(p), "f"(m.x), "f"(m.y), "f"(m.z), "f"(m.w)
                 : "memory");
}

// ---------------------------------------------------------------------------
// Kernel 2: tiled per-block MLP.  out = relu((x+agg) @ W1 + b1) @ W2 + b2
//
// Block = 128 threads, tile = 32 nodes (100000 = 3125 * 32 exactly).
// h = x + agg fused into the tile-staging loads. Each thread owns
// 4 nodes x 4 cols, held as 8 packed f32x2 accumulators -> 8 FFMA2 per k
// instead of 16 FFMA (fma pipe is the binder; halving its instr count
// ~halves the kernel).
// ---------------------------------------------------------------------------
#define TILE_N 32
#define HPAD 68          // padded row stride (floats), kills bank conflicts

// One 64x64 GEMM tile pass over hs with packed accumulators.
// acc01[c]: col cg*4+c for nodes (ng*4+0, ng*4+1); acc23: nodes +2,+3.
__device__ __forceinline__ void gemm_pass(const float* hs, const float4* Ws4,
                                          float4 bv, int ng, int cg,
                                          unsigned long long acc01[4],
                                          unsigned long long acc23[4]) {
    acc01[0] = pk2(bv.x, bv.x); acc23[0] = acc01[0];
    acc01[1] = pk2(bv.y, bv.y); acc23[1] = acc01[1];
    acc01[2] = pk2(bv.z, bv.z); acc23[2] = acc01[2];
    acc01[3] = pk2(bv.w, bv.w); acc23[3] = acc01[3];

    const float* h0p = hs + (ng * 4 + 0) * HPAD;
    const float* h1p = hs + (ng * 4 + 1) * HPAD;
    const float* h2p = hs + (ng * 4 + 2) * HPAD;
    const float* h3p = hs + (ng * 4 + 3) * HPAD;

    #pragma unroll
    for (int k = 0; k < D; ++k) {
        float4 w = Ws4[k * (D / 4) + cg];
        unsigned long long wxx = pk2(w.x, w.x);
        unsigned long long wyy = pk2(w.y, w.y);
        unsigned long long wzz = pk2(w.z, w.z);
        unsigned long long www = pk2(w.w, w.w);
        unsigned long long h01 = pk2(h0p[k], h1p[k]);
        unsigned long long h23 = pk2(h2p[k], h3p[k]);

        acc01[0] = ffma2(h01, wxx, acc01[0]);
        acc01[1] = ffma2(h01, wyy, acc01[1]);
        acc01[2] = ffma2(h01, wzz, acc01[2]);
        acc01[3] = ffma2(h01, www, acc01[3]);
        acc23[0] = ffma2(h23, wxx, acc23[0]);
        acc23[1] = ffma2(h23, wyy, acc23[1]);
        acc23[2] = ffma2(h23, wzz, acc23[2]);
        acc23[3] = ffma2(h23, www, acc23[3]);
    }
}

__global__ void __launch_bounds__(128)
mlp_kernel(const float* __restrict__ x,
           const float* __restrict__ W1, const float* __restrict__ b1,
           const float* __restrict__ W2, const float* __restrict__ b2,
           float* __restrict__ out) {
    __shared__ float hs[TILE_N * HPAD];          // 8.5 KB
    __shared__ float W1s[D * D];                 // 16 KB
    __shared__ float W2s[D * D];                 // 16 KB
    __shared__ float b1s[D];
    __shared__ float b2s[D];

    const int tid = threadIdx.x;
    const int node0 = blockIdx.x * TILE_N;

    // Stage weights + biases.
    {
        const float4* w1g = reinterpret_cast<const float4*>(W1);
        const float4* w2g = reinterpret_cast<const float4*>(W2);
        float4* w1s = reinterpret_cast<float4*>(W1s);
        float4* w2s = reinterpret_cast<float4*>(W2s);
        #pragma unroll
        for (int i = tid; i < D * D / 4; i += 128) {
            w1s[i] = w1g[i];
            w2s[i] = w2g[i];
        }
        if (tid < D) { b1s[tid] = b1[tid]; b2s[tid] = b2[tid]; }
    }

    // Stage h tile = x + agg (EPS=0): 32 nodes x 16 float4, 4 per thread.
    {
        const float4* ag = reinterpret_cast<const float4*>(g_agg);
        const float4* xg = reinterpret_cast<const float4*>(x);
        #pragma unroll
        for (int i = tid; i < TILE_N * (D / 4); i += 128) {
            int n = i >> 4;          // node within tile
            int c = i & 15;          // float4 chunk
            size_t gi = (size_t)(node0 + n) * (D / 4) + c;
            float4 a = ag[gi];
            float4 v = __ldg(xg + gi);
            a.x += v.x; a.y += v.y; a.z += v.z; a.w += v.w;
            *reinterpret_cast<float4*>(&hs[n * HPAD + c * 4]) = a;
        }
    }
    __syncthreads();

    const int cg = tid & 15;         // column group: cols cg*4 .. cg*4+3
    const int ng = tid >> 4;         // node group:   nodes ng*4 .. ng*4+3
    const float4* W1s4 = reinterpret_cast<const float4*>(W1s);
    const float4* W2s4 = reinterpret_cast<const float4*>(W2s);

    unsigned long long acc01[4], acc23[4];

    // ---- Layer 1: t = relu(h @ W1 + b1) ----
    gemm_pass(hs, W1s4, reinterpret_cast<const float4*>(b1s)[cg], ng, cg,
              acc01, acc23);

    float4 r0, r1, r2, r3;
    upk2(acc01[0], r0.x, r1.x); upk2(acc01[1], r0.y, r1.y);
    upk2(acc01[2], r0.z, r1.z); upk2(acc01[3], r0.w, r1.w);
    upk2(acc23[0], r2.x, r3.x); upk2(acc23[1], r2.y, r3.y);
    upk2(acc23[2], r2.z, r3.z); upk2(acc23[3], r2.w, r3.w);
    r0.x = fmaxf(r0.x, 0.f); r0.y = fmaxf(r0.y, 0.f); r0.z = fmaxf(r0.z, 0.f); r0.w = fmaxf(r0.w, 0.f);
    r1.x = fmaxf(r1.x, 0.f); r1.y = fmaxf(r1.y, 0.f); r1.z = fmaxf(r1.z, 0.f); r1.w = fmaxf(r1.w, 0.f);
    r2.x = fmaxf(r2.x, 0.f); r2.y = fmaxf(r2.y, 0.f); r2.z = fmaxf(r2.z, 0.f); r2.w = fmaxf(r2.w, 0.f);
    r3.x = fmaxf(r3.x, 0.f); r3.y = fmaxf(r3.y, 0.f); r3.z = fmaxf(r3.z, 0.f); r3.w = fmaxf(r3.w, 0.f);

    __syncthreads();   // everyone done reading hs
    *reinterpret_cast<float4*>(&hs[(ng * 4 + 0) * HPAD + cg * 4]) = r0;
    *reinterpret_cast<float4*>(&hs[(ng * 4 + 1) * HPAD + cg * 4]) = r1;
    *reinterpret_cast<float4*>(&hs[(ng * 4 + 2) * HPAD + cg * 4]) = r2;
    *reinterpret_cast<float4*>(&hs[(ng * 4 + 3) * HPAD + cg * 4]) = r3;
    __syncthreads();

    // ---- Layer 2: out = t @ W2 + b2 ----
    gemm_pass(hs, W2s4, reinterpret_cast<const float4*>(b2s)[cg], ng, cg,
              acc01, acc23);

    upk2(acc01[0], r0.x, r1.x); upk2(acc01[1], r0.y, r1.y);
    upk2(acc01[2], r0.z, r1.z); upk2(acc01[3], r0.w, r1.w);
    upk2(acc23[0], r2.x, r3.x); upk2(acc23[1], r2.y, r3.y);
    upk2(acc23[2], r2.z, r3.z); upk2(acc23[3], r2.w, r3.w);

    float4* ob = reinterpret_cast<float4*>(out);
    ob[(size_t)(node0 + ng * 4 + 0) * (D / 4) + cg] = r0;
    ob[(size_t)(node0 + ng * 4 + 1) * (D / 4) + cg] = r1;
    ob[(size_t)(node0 + ng * 4 + 2) * (D / 4) + cg] = r2;
    ob[(size_t)(node0 + ng * 4 + 3) * (D / 4) + cg] = r3;
}

// ---------------------------------------------------------------------------
// Launch. Inputs: x f32[100000*64], edge_index i32[2*1200000],
// edge_attr f32[1200000*64], W1 f32[64*64], b1 f32[64], W2 f32[64*64],
// b2 f32[64]. Output f32[100000*64].
// ---------------------------------------------------------------------------
extern "C" void kernel_launch(void* const* d_in, const int* in_sizes, int n_in,
                              void* d_out, int out_size) {
    const float* x   = (const float*)d_in[0];
    const int*   ei  = (const int*)d_in[1];
    const float* ea  = (const float*)d_in[2];
    const float* W1  = (const float*)d_in[3];
    const float* b1  = (const float*)d_in[4];
    const float* W2  = (const float*)d_in[5];
    const float* b2  = (const float*)d_in[6];
    float*       out = (float*)d_out;

    // agg <- 0 (write-only, full write BW; graph-capturable memset)
    void* aggp = nullptr;
    cudaGetSymbolAddress(&aggp, g_agg);
    cudaMemsetAsync(aggp, 0, sizeof(float) * (size_t)N_NODES * D);

    {   // scatter-sum messages
        int total = N_EDGES * 16;
        edge_kernel<<<(total + 255) / 256, 256>>>(x, ei, ea);
    }
    {   // fused (x+agg) -> MLP: 100000 / 32 = 3125 blocks
        mlp_kernel<<<N_NODES / TILE_N, 128>>>(x, W1, b1, W2, b2, out);
    }
}

// round 10
// speedup vs baseline: 1.0154x; 1.0021x over previous
#include <cuda_runtime.h>
#include <cuda_bf16.h>
#include <stdint.h>

#define N_NODES 100000
#define N_EDGES 1200000
#define D 64

// Persistent scratch: agg = scatter_sum(relu(x[src] + e)); zeroed by memset
// each call. 16B-aligned for red.global.add.v4.f32.
__device__ __align__(16) float g_agg[(size_t)N_NODES * D];

// ---------------------------------------------------------------------------
// f32x2 packed-FMA helpers (FFMA2 — PTX-only, sm_100+)
// ---------------------------------------------------------------------------
__device__ __forceinline__ unsigned long long pk2(float lo, float hi) {
    unsigned long long r;
    asm("mov.b64 %0, {%1, %2};" : "=l"(r) : "f"(lo), "f"(hi));
    return r;
}
__device__ __forceinline__ unsigned long long ffma2(unsigned long long a,
                                                    unsigned long long b,
                                                    unsigned long long c) {
    unsigned long long d;
    asm("fma.rn.f32x2 %0, %1, %2, %3;" : "=l"(d) : "l"(a), "l"(b), "l"(c));
    return d;
}
__device__ __forceinline__ void upk2(unsigned long long v, float& lo, float& hi) {
    asm("mov.b64 {%0, %1}, %2;" : "=f"(lo), "=f"(hi) : "l"(v));
}

// ---------------------------------------------------------------------------
// Kernel 1: per-edge message + scatter reduce (unchanged; L2-transit bound).
// 16 threads per edge, one float4 chunk each.
// ---------------------------------------------------------------------------
__global__ void edge_kernel(const float* __restrict__ x,
                            const int* __restrict__ ei,
                            const float* __restrict__ ea) {
    int t = blockIdx.x * blockDim.x + threadIdx.x;
    const int total = N_EDGES * 16;
    if (t >= total) return;
    int e = t >> 4;        // edge id
    int c = t & 15;        // float4 chunk within row

    int src = __ldg(ei + e);
    int dst = __ldg(ei + N_EDGES + e);

    float4 xv = __ldg(reinterpret_cast<const float4*>(x) + (size_t)src * (D / 4) + c);
    float4 ev = __ldcs(reinterpret_cast<const float4*>(ea) + (size_t)e * (D / 4) + c);

    float4 m;
    m.x = fmaxf(xv.x + ev.x, 0.0f);
    m.y = fmaxf(xv.y + ev.y, 0.0f);
    m.z = fmaxf(xv.z + ev.z, 0.0f);
    m.w = fmaxf(xv.w + ev.w, 0.0f);

    float* p = g_agg + (size_t)dst * D + c * 4;
    asm volatile("red.global.add.v4.f32 [%0], {%1, %2, %3, %4};"
                 :: "l"(p), "f"(m.x), "f"(m.y), "f"(m.z), "f"(m.w)
                 : "memory");
}

// ---------------------------------------------------------------------------
// Kernel 2: tiled MLP.  out = relu((x+agg) @ W1 + b1) @ W2 + b2
//
// Block = 128 threads, tile = 32 nodes (100000 = 3125 * 32).
// h tile stored TRANSPOSED: hsT[k][node] (padded row of 36 floats).
// Thread owns 4 nodes x 4 cols. Accumulators packed over COLUMN pairs:
//   - W operand pairs {w_c0,w_c1},{w_c2,w_c3} come straight from one LDS.128
//     (row-major W) reinterpreted as ulonglong2 — zero pack instructions.
//   - h operand: one LDS.128 per k gives all 4 node values; 4 dup-packs
//     {h,h} per k are the only ALU cost (half the FFMA2 count -> fma binds).
// Per k per thread: 2 LDS + 4 ALU + 8 FFMA2.
// ---------------------------------------------------------------------------
#define TILE_N 32
#define HT_PAD 36        // floats per hsT row: 144B, 16B-aligned, bank-skewed

__device__ __forceinline__ void gemm_pass_T(const float* hsT, const float4* Ws4,
                                            float4 bv, int ng, int cg,
                                            unsigned long long acc[4][2]) {
    unsigned long long b01 = pk2(bv.x, bv.y);
    unsigned long long b23 = pk2(bv.z, bv.w);
    #pragma unroll
    for (int n = 0; n < 4; ++n) { acc[n][0] = b01; acc[n][1] = b23; }

    #pragma unroll 16
    for (int k = 0; k < D; ++k) {
        float4 hv = *reinterpret_cast<const float4*>(hsT + k * HT_PAD + ng * 4);
        ulonglong2 wp = *reinterpret_cast<const ulonglong2*>(Ws4 + k * (D / 4) + cg);
        unsigned long long h0 = pk2(hv.x, hv.x);
        unsigned long long h1 = pk2(hv.y, hv.y);
        unsigned long long h2 = pk2(hv.z, hv.z);
        unsigned long long h3 = pk2(hv.w, hv.w);
        acc[0][0] = ffma2(h0, wp.x, acc[0][0]);
        acc[0][1] = ffma2(h0, wp.y, acc[0][1]);
        acc[1][0] = ffma2(h1, wp.x, acc[1][0]);
        acc[1][1] = ffma2(h1, wp.y, acc[1][1]);
        acc[2][0] = ffma2(h2, wp.x, acc[2][0]);
        acc[2][1] = ffma2(h2, wp.y, acc[2][1]);
        acc[3][0] = ffma2(h3, wp.x, acc[3][0]);
        acc[3][1] = ffma2(h3, wp.y, acc[3][1]);
    }
}

__global__ void __launch_bounds__(128)
mlp_kernel(const float* __restrict__ x,
           const float* __restrict__ W1, const float* __restrict__ b1,
           const float* __restrict__ W2, const float* __restrict__ b2,
           float* __restrict__ out) {
    __shared__ float hsT[D * HT_PAD];            // 9.2 KB, transposed h tile
    __shared__ float W1s[D * D];                 // 16 KB
    __shared__ float W2s[D * D];                 // 16 KB

    const int tid = threadIdx.x;
    const int node0 = blockIdx.x * TILE_N;
    const int cg = tid & 15;         // column group: cols cg*4 .. cg*4+3
    const int ng = tid >> 4;         // node group:   nodes ng*4 .. ng*4+3

    // Biases straight from global (L2-cached, read once per thread).
    float4 bv1 = __ldg(reinterpret_cast<const float4*>(b1) + cg);
    float4 bv2 = __ldg(reinterpret_cast<const float4*>(b2) + cg);

    // Stage weights.
    {
        const float4* w1g = reinterpret_cast<const float4*>(W1);
        const float4* w2g = reinterpret_cast<const float4*>(W2);
        float4* w1s = reinterpret_cast<float4*>(W1s);
        float4* w2s = reinterpret_cast<float4*>(W2s);
        #pragma unroll
        for (int i = tid; i < D * D / 4; i += 128) {
            w1s[i] = w1g[i];
            w2s[i] = w2g[i];
        }
    }

    // Stage h tile = x + agg (EPS=0), transposed into hsT[k][n].
    {
        const float4* ag = reinterpret_cast<const float4*>(g_agg);
        const float4* xg = reinterpret_cast<const float4*>(x);
        #pragma unroll
        for (int i = tid; i < TILE_N * (D / 4); i += 128) {
            int n = i >> 4;          // node within tile
            int c = i & 15;          // float4 chunk (cols c*4..c*4+3)
            size_t gi = (size_t)(node0 + n) * (D / 4) + c;
            float4 a = ag[gi];
            float4 v = __ldg(xg + gi);
            a.x += v.x; a.y += v.y; a.z += v.z; a.w += v.w;
            hsT[(c * 4 + 0) * HT_PAD + n] = a.x;
            hsT[(c * 4 + 1) * HT_PAD + n] = a.y;
            hsT[(c * 4 + 2) * HT_PAD + n] = a.z;
            hsT[(c * 4 + 3) * HT_PAD + n] = a.w;
        }
    }
    __syncthreads();

    const float4* W1s4 = reinterpret_cast<const float4*>(W1s);
    const float4* W2s4 = reinterpret_cast<const float4*>(W2s);

    unsigned long long acc[4][2];
    float o[4][4];   // [node][col]

    // ---- Layer 1: t = relu(h @ W1 + b1) ----
    gemm_pass_T(hsT, W1s4, bv1, ng, cg, acc);
    #pragma unroll
    for (int n = 0; n < 4; ++n) {
        upk2(acc[n][0], o[n][0], o[n][1]);
        upk2(acc[n][1], o[n][2], o[n][3]);
        #pragma unroll
        for (int j = 0; j < 4; ++j) o[n][j] = fmaxf(o[n][j], 0.0f);
    }
    __syncthreads();   // everyone done reading hsT

    // Write t back transposed: hsT[col][node], vector over the 4 nodes.
    #pragma unroll
    for (int j = 0; j < 4; ++j) {
        float4 v = make_float4(o[0][j], o[1][j], o[2][j], o[3][j]);
        *reinterpret_cast<float4*>(&hsT[(cg * 4 + j) * HT_PAD + ng * 4]) = v;
    }
    __syncthreads();

    // ---- Layer 2: out = t @ W2 + b2 ----
    gemm_pass_T(hsT, W2s4, bv2, ng, cg, acc);
    #pragma unroll
    for (int n = 0; n < 4; ++n) {
        upk2(acc[n][0], o[n][0], o[n][1]);
        upk2(acc[n][1], o[n][2], o[n][3]);
    }

    float4* ob = reinterpret_cast<float4*>(out);
    #pragma unroll
    for (int n = 0; n < 4; ++n) {
        float4 v = make_float4(o[n][0], o[n][1], o[n][2], o[n][3]);
        ob[(size_t)(node0 + ng * 4 + n) * (D / 4) + cg] = v;
    }
}

// ---------------------------------------------------------------------------
// Launch. Inputs: x f32[100000*64], edge_index i32[2*1200000],
// edge_attr f32[1200000*64], W1 f32[64*64], b1 f32[64], W2 f32[64*64],
// b2 f32[64]. Output f32[100000*64].
// ---------------------------------------------------------------------------
extern "C" void kernel_launch(void* const* d_in, const int* in_sizes, int n_in,
                              void* d_out, int out_size) {
    const float* x   = (const float*)d_in[0];
    const int*   ei  = (const int*)d_in[1];
    const float* ea  = (const float*)d_in[2];
    const float* W1  = (const float*)d_in[3];
    const float* b1  = (const float*)d_in[4];
    const float* W2  = (const float*)d_in[5];
    const float* b2  = (const float*)d_in[6];
    float*       out = (float*)d_out;

    // agg <- 0 (write-only; graph-capturable memset)
    void* aggp = nullptr;
    cudaGetSymbolAddress(&aggp, g_agg);
    cudaMemsetAsync(aggp, 0, sizeof(float) * (size_t)N_NODES * D);

    {   // scatter-sum messages
        int total = N_EDGES * 16;
        edge_kernel<<<(total + 255) / 256, 256>>>(x, ei, ea);
    }
    {   // fused (x+agg) -> MLP: 3125 blocks
        mlp_kernel<<<N_NODES / TILE_N, 128>>>(x, W1, b1, W2, b2, out);
    }
}

// round 11
// speedup vs baseline: 1.0469x; 1.0310x over previous
#include <cuda_runtime.h>
#include <cuda_bf16.h>
#include <stdint.h>

#define N_NODES 100000
#define N_EDGES 1200000
#define D 64

// Persistent scratch: agg = scatter_sum(relu(x[src] + e)); zeroed by memset.
__device__ __align__(16) float g_agg[(size_t)N_NODES * D];

// ---------------------------------------------------------------------------
// f32x2 packed-FMA helpers (FFMA2 — PTX-only, sm_100+)
// ---------------------------------------------------------------------------
__device__ __forceinline__ unsigned long long pk2(float lo, float hi) {
    unsigned long long r;
    asm("mov.b64 %0, {%1, %2};" : "=l"(r) : "f"(lo), "f"(hi));
    return r;
}
__device__ __forceinline__ unsigned long long ffma2(unsigned long long a,
                                                    unsigned long long b,
                                                    unsigned long long c) {
    unsigned long long d;
    asm("fma.rn.f32x2 %0, %1, %2, %3;" : "=l"(d) : "l"(a), "l"(b), "l"(c));
    return d;
}
__device__ __forceinline__ void upk2(unsigned long long v, float& lo, float& hi) {
    asm("mov.b64 {%0, %1}, %2;" : "=f"(lo), "=f"(hi) : "l"(v));
}

// ---------------------------------------------------------------------------
// Kernel 1: per-edge message + scatter reduce (L2-transit bound, unchanged).
// ---------------------------------------------------------------------------
__global__ void edge_kernel(const float* __restrict__ x,
                            const int* __restrict__ ei,
                            const float* __restrict__ ea) {
    int t = blockIdx.x * blockDim.x + threadIdx.x;
    const int total = N_EDGES * 16;
    if (t >= total) return;
    int e = t >> 4;
    int c = t & 15;

    int src = __ldg(ei + e);
    int dst = __ldg(ei + N_EDGES + e);

    float4 xv = __ldg(reinterpret_cast<const float4*>(x) + (size_t)src * (D / 4) + c);
    float4 ev = __ldcs(reinterpret_cast<const float4*>(ea) + (size_t)e * (D / 4) + c);

    float4 m;
    m.x = fmaxf(xv.x + ev.x, 0.0f);
    m.y = fmaxf(xv.y + ev.y, 0.0f);
    m.z = fmaxf(xv.z + ev.z, 0.0f);
    m.w = fmaxf(xv.w + ev.w, 0.0f);

    float* p = g_agg + (size_t)dst * D + c * 4;
    asm volatile("red.global.add.v4.f32 [%0], {%1, %2, %3, %4};"
                 :: "l"(p), "f"(m.x), "f"(m.y), "f"(m.z), "f"(m.w)
                 : "memory");
}

// ---------------------------------------------------------------------------
// Kernel 2: tiled MLP.  out = relu((x+agg) @ W1 + b1) @ W2 + b2
//
// Block = 128 threads, TILE_N = 128 nodes. Thread owns 8 nodes x 8 cols
// (cols cg*4..+3 and 32+cg*4..+3). Per k: 4 LDS.128 feed 32 FFMA2.
//   hv: hsT[k][ng*8..+7] — 4 unique addrs/warp, broadcast, conflict-free.
//   wp: W row k, 8 lanes x 16B contiguous per load — conflict-free.
// hsT transposed with 132-float row pad. Single W smem buffer; W2 reloaded
// between layers. Dynamic smem 50.2 KB -> 4 blocks/SM.
// ---------------------------------------------------------------------------
#define TILE_N 128
#define HT_PAD 132
#define SMEM_HST_FLOATS (D * HT_PAD)             // 8448
#define SMEM_TOTAL_BYTES ((SMEM_HST_FLOATS + D * D) * 4)   // 50176

extern __shared__ float smem_dyn[];

// acc[n][p]: node ng*8+n; p=0,1 -> col pairs (cg*4+0,+1),(cg*4+2,+3);
//            p=2,3 -> (32+cg*4+0,+1),(32+cg*4+2,+3)
__device__ __forceinline__ void gemm_pass(const float* hsT, const float* Ws,
                                          int ng, int cg,
                                          unsigned long long acc[8][4]) {
    #pragma unroll 8
    for (int k = 0; k < D; ++k) {
        const float* hrow = hsT + k * HT_PAD + ng * 8;
        float4 hv0 = *reinterpret_cast<const float4*>(hrow);
        float4 hv1 = *reinterpret_cast<const float4*>(hrow + 4);
        ulonglong2 wp0 = *reinterpret_cast<const ulonglong2*>(Ws + k * D + cg * 4);
        ulonglong2 wp1 = *reinterpret_cast<const ulonglong2*>(Ws + k * D + 32 + cg * 4);

        unsigned long long h[8];
        h[0] = pk2(hv0.x, hv0.x); h[1] = pk2(hv0.y, hv0.y);
        h[2] = pk2(hv0.z, hv0.z); h[3] = pk2(hv0.w, hv0.w);
        h[4] = pk2(hv1.x, hv1.x); h[5] = pk2(hv1.y, hv1.y);
        h[6] = pk2(hv1.z, hv1.z); h[7] = pk2(hv1.w, hv1.w);

        #pragma unroll
        for (int n = 0; n < 8; ++n) {
            acc[n][0] = ffma2(h[n], wp0.x, acc[n][0]);
            acc[n][1] = ffma2(h[n], wp0.y, acc[n][1]);
            acc[n][2] = ffma2(h[n], wp1.x, acc[n][2]);
            acc[n][3] = ffma2(h[n], wp1.y, acc[n][3]);
        }
    }
}

__global__ void __launch_bounds__(128)
mlp_kernel(const float* __restrict__ x,
           const float* __restrict__ W1, const float* __restrict__ b1,
           const float* __restrict__ W2, const float* __restrict__ b2,
           float* __restrict__ out) {
    float* hsT = smem_dyn;                       // [D][HT_PAD]
    float* Ws  = smem_dyn + SMEM_HST_FLOATS;     // [D][D]

    const int tid = threadIdx.x;
    const int node0 = blockIdx.x * TILE_N;
    const int cg = tid & 7;          // col group
    const int ng = tid >> 3;         // node group (0..15)

    // Stage W1.
    {
        const float4* wg = reinterpret_cast<const float4*>(W1);
        float4* ws = reinterpret_cast<float4*>(Ws);
        #pragma unroll
        for (int i = tid; i < D * D / 4; i += 128) ws[i] = wg[i];
    }
    // Stage h tile = x + agg, transposed into hsT[k][n]. Tail: clamp node.
    {
        const float4* ag = reinterpret_cast<const float4*>(g_agg);
        const float4* xg = reinterpret_cast<const float4*>(x);
        #pragma unroll
        for (int i = tid; i < TILE_N * (D / 4); i += 128) {
            int n = i >> 4;          // node within tile
            int c = i & 15;          // float4 chunk
            int node = node0 + n;
            if (node >= N_NODES) node = N_NODES - 1;
            size_t gi = (size_t)node * (D / 4) + c;
            float4 a = ag[gi];
            float4 v = __ldg(xg + gi);
            a.x += v.x; a.y += v.y; a.z += v.z; a.w += v.w;
            hsT[(c * 4 + 0) * HT_PAD + n] = a.x;
            hsT[(c * 4 + 1) * HT_PAD + n] = a.y;
            hsT[(c * 4 + 2) * HT_PAD + n] = a.z;
            hsT[(c * 4 + 3) * HT_PAD + n] = a.w;
        }
    }
    __syncthreads();

    // Bias pairs for this thread's 8 cols.
    float4 b1a = __ldg(reinterpret_cast<const float4*>(b1) + cg);
    float4 b1b = __ldg(reinterpret_cast<const float4*>(b1) + 8 + cg);
    float4 b2a = __ldg(reinterpret_cast<const float4*>(b2) + cg);
    float4 b2b = __ldg(reinterpret_cast<const float4*>(b2) + 8 + cg);

    unsigned long long acc[8][4];

    // ---- Layer 1: t = relu(h @ W1 + b1) ----
    {
        unsigned long long i0 = pk2(b1a.x, b1a.y), i1 = pk2(b1a.z, b1a.w);
        unsigned long long i2 = pk2(b1b.x, b1b.y), i3 = pk2(b1b.z, b1b.w);
        #pragma unroll
        for (int n = 0; n < 8; ++n) {
            acc[n][0] = i0; acc[n][1] = i1; acc[n][2] = i2; acc[n][3] = i3;
        }
    }
    gemm_pass(hsT, Ws, ng, cg, acc);

    float o[8][8];   // [node][col-within-thread]
    #pragma unroll
    for (int n = 0; n < 8; ++n) {
        upk2(acc[n][0], o[n][0], o[n][1]);
        upk2(acc[n][1], o[n][2], o[n][3]);
        upk2(acc[n][2], o[n][4], o[n][5]);
        upk2(acc[n][3], o[n][6], o[n][7]);
        #pragma unroll
        for (int j = 0; j < 8; ++j) o[n][j] = fmaxf(o[n][j], 0.0f);
    }

    __syncthreads();   // done reading hsT + Ws(W1)

    // Write t back transposed; reload Ws with W2.
    #pragma unroll
    for (int j = 0; j < 8; ++j) {
        int col = (j < 4) ? (cg * 4 + j) : (32 + cg * 4 + (j - 4));
        float* r = hsT + col * HT_PAD + ng * 8;
        *reinterpret_cast<float4*>(r)     = make_float4(o[0][j], o[1][j], o[2][j], o[3][j]);
        *reinterpret_cast<float4*>(r + 4) = make_float4(o[4][j], o[5][j], o[6][j], o[7][j]);
    }
    {
        const float4* wg = reinterpret_cast<const float4*>(W2);
        float4* ws = reinterpret_cast<float4*>(Ws);
        #pragma unroll
        for (int i = tid; i < D * D / 4; i += 128) ws[i] = wg[i];
    }
    __syncthreads();

    // ---- Layer 2: out = t @ W2 + b2 ----
    {
        unsigned long long i0 = pk2(b2a.x, b2a.y), i1 = pk2(b2a.z, b2a.w);
        unsigned long long i2 = pk2(b2b.x, b2b.y), i3 = pk2(b2b.z, b2b.w);
        #pragma unroll
        for (int n = 0; n < 8; ++n) {
            acc[n][0] = i0; acc[n][1] = i1; acc[n][2] = i2; acc[n][3] = i3;
        }
    }
    gemm_pass(hsT, Ws, ng, cg, acc);

    float4* ob = reinterpret_cast<float4*>(out);
    #pragma unroll
    for (int n = 0; n < 8; ++n) {
        int node = node0 + ng * 8 + n;
        if (node < N_NODES) {
            float a, b, c, d2;
            upk2(acc[n][0], a, b); upk2(acc[n][1], c, d2);
            ob[(size_t)node * (D / 4) + cg] = make_float4(a, b, c, d2);
            upk2(acc[n][2], a, b); upk2(acc[n][3], c, d2);
            ob[(size_t)node * (D / 4) + 8 + cg] = make_float4(a, b, c, d2);
        }
    }
}

// ---------------------------------------------------------------------------
// Launch.
// ---------------------------------------------------------------------------
extern "C" void kernel_launch(void* const* d_in, const int* in_sizes, int n_in,
                              void* d_out, int out_size) {
    const float* x   = (const float*)d_in[0];
    const int*   ei  = (const int*)d_in[1];
    const float* ea  = (const float*)d_in[2];
    const float* W1  = (const float*)d_in[3];
    const float* b1  = (const float*)d_in[4];
    const float* W2  = (const float*)d_in[5];
    const float* b2  = (const float*)d_in[6];
    float*       out = (float*)d_out;

    // agg <- 0 (graph-capturable)
    void* aggp = nullptr;
    cudaGetSymbolAddress(&aggp, g_agg);
    cudaMemsetAsync(aggp, 0, sizeof(float) * (size_t)N_NODES * D);

    {   // scatter-sum messages
        int total = N_EDGES * 16;
        edge_kernel<<<(total + 255) / 256, 256>>>(x, ei, ea);
    }
    {   // fused (x+agg) -> MLP; 782 blocks cover 100096 slots (tail guarded)
        static bool attr_set = false;
        if (!attr_set) {
            cudaFuncSetAttribute(mlp_kernel,
                                 cudaFuncAttributeMaxDynamicSharedMemorySize,
                                 SMEM_TOTAL_BYTES);
            attr_set = true;
        }
        int grid = (N_NODES + TILE_N - 1) / TILE_N;
        mlp_kernel<<<grid, 128, SMEM_TOTAL_BYTES>>>(x, W1, b1, W2, b2, out);
    }
}